// round 3
// baseline (speedup 1.0000x reference)
#include <cuda_runtime.h>
#include <cstdint>

#define BB   8
#define CC   256
#define HH   96
#define WW   96
#define RR   64
#define HWSZ 9216
#define GG   16
#define KK   49
#define PH   102          // padded height (96 + 6)
#define PW   104          // padded width  (96 + 6 -> round to 104 for 16B rows)

__device__ float g_x[BB * RR * HWSZ];                 // relu(bn(W1@guide))
__device__ float g_fmp[(size_t)BB * CC * PH * PW];    // zero-padded feature map

typedef unsigned long long u64;

// ---------- packed f32x2 helpers (Blackwell sm_10x) ----------
__device__ __forceinline__ u64 pack2(float lo, float hi) {
    u64 r;
    asm("mov.b64 %0, {%1, %2};" : "=l"(r) : "f"(lo), "f"(hi));
    return r;
}
__device__ __forceinline__ void unpack2(u64 v, float& lo, float& hi) {
    asm("mov.b64 {%0, %1}, %2;" : "=f"(lo), "=f"(hi) : "l"(v));
}
__device__ __forceinline__ void fma2(u64& d, u64 a, u64 b) {
    asm("fma.rn.f32x2 %0, %1, %2, %0;" : "+l"(d) : "l"(a), "l"(b));
}

// ---------- cp.async helpers ----------
__device__ __forceinline__ unsigned s2u(const void* p) {
    return (unsigned)__cvta_generic_to_shared(p);
}
__device__ __forceinline__ void cp16(void* dst, const void* src) {
    asm volatile("cp.async.cg.shared.global [%0], [%1], 16;\n"
                 :: "r"(s2u(dst)), "l"(src));
}
__device__ __forceinline__ void cp_commit() {
    asm volatile("cp.async.commit_group;\n" ::);
}
template<int N> __device__ __forceinline__ void cp_wait() {
    asm volatile("cp.async.wait_group %0;\n" :: "n"(N));
}

// =====================================================================
// Kernel 0: zero-padded copy fm[b][c][96][96] -> g_fmp[b][c][102][104]
// one float4 of the padded image per thread.
// =====================================================================
#define PAD_TOT (BB * CC * PH * (PW / 4))    // 5,431,296

__global__ void __launch_bounds__(256)
k0_pad(const float* __restrict__ fm)
{
    int idx = blockIdx.x * 256 + threadIdx.x;
    if (idx >= PAD_TOT) return;
    int c4  = idx % (PW / 4);
    int r   = (idx / (PW / 4)) % PH;
    int ch  = idx / ((PW / 4) * PH);

    float4 v = make_float4(0.f, 0.f, 0.f, 0.f);
    int i = r - 3;
    if ((unsigned)i < 96u) {
        const float* src = fm + (size_t)ch * HWSZ + i * WW;
        int j0 = c4 * 4 - 3;
#pragma unroll
        for (int e = 0; e < 4; ++e) {
            int j = j0 + e;
            if ((unsigned)j < 96u) (&v.x)[e] = src[j];
        }
    }
    ((float4*)g_fmp)[idx] = v;
}

// =====================================================================
// Kernel 1: x[b,r,p] = relu(a[r]*(W1[r,:].guide[b,:,p]) + c[r])
// (unchanged from R2 — near FMA floor)
// =====================================================================
#define K1_WS 16384
#define K1_GS 4096
#define K1_SMEM ((K1_WS + 2 * K1_GS) * 4)

__global__ void __launch_bounds__(256, 2)
k1_gemm_bn_relu(const float* __restrict__ guide, const float* __restrict__ W1,
                const float* __restrict__ gamma_, const float* __restrict__ beta_,
                const float* __restrict__ mean_, const float* __restrict__ var_)
{
    extern __shared__ float sm1[];
    float* Ws = sm1;
    float* Gs = sm1 + K1_WS;

    const int tid = threadIdx.x;
    const int b   = blockIdx.y;
    const int p0  = blockIdx.x * 256;
    const float* gb = guide + (size_t)b * CC * HWSZ + p0;

    for (int i = tid; i < 4096; i += 256)
        cp16(Ws + i * 4, W1 + i * 4);
    for (int i = tid; i < 1024; i += 256) {
        int kr = i >> 6, c4 = i & 63;
        cp16(Gs + kr * 256 + c4 * 4, gb + kr * HWSZ + c4 * 4);
    }
    cp_commit();

    u64 acc[8][4];
#pragma unroll
    for (int i = 0; i < 8; ++i)
#pragma unroll
        for (int j = 0; j < 4; ++j) acc[i][j] = 0ull;

    const int pc = tid & 31;
    const int rg = tid >> 5;

    for (int kc = 0; kc < 16; ++kc) {
        if (kc < 15) {
            float* dst = Gs + ((kc + 1) & 1) * K1_GS;
            const float* src = gb + (size_t)(kc + 1) * 16 * HWSZ;
            for (int i = tid; i < 1024; i += 256) {
                int kr = i >> 6, c4 = i & 63;
                cp16(dst + kr * 256 + c4 * 4, src + kr * HWSZ + c4 * 4);
            }
            cp_commit();
            cp_wait<1>();
        } else {
            cp_wait<0>();
        }
        __syncthreads();

        const float* G  = Gs + (kc & 1) * K1_GS;
        const float* Wr = Ws + (rg * 8) * 256 + kc * 16;
#pragma unroll
        for (int kk = 0; kk < 16; kk += 4) {
            float4 wv[8];
#pragma unroll
            for (int i = 0; i < 8; ++i)
                wv[i] = *(const float4*)(Wr + i * 256 + kk);
#pragma unroll
            for (int t = 0; t < 4; ++t) {
                u64 bv[4];
#pragma unroll
                for (int j = 0; j < 4; ++j)
                    bv[j] = *(const u64*)(G + (kk + t) * 256 + 2 * (pc + 32 * j));
#pragma unroll
                for (int i = 0; i < 8; ++i) {
                    float w = (&wv[i].x)[t];
                    u64 wq = pack2(w, w);
#pragma unroll
                    for (int j = 0; j < 4; ++j) fma2(acc[i][j], wq, bv[j]);
                }
            }
        }
        __syncthreads();
    }

#pragma unroll
    for (int i = 0; i < 8; ++i) {
        int r = rg * 8 + i;
        float a = gamma_[r] * rsqrtf(var_[r] + 1e-5f);
        float c = beta_[r] - mean_[r] * a;
        float* xb = g_x + ((size_t)b * RR + r) * HWSZ + p0;
#pragma unroll
        for (int j = 0; j < 4; ++j) {
            float lo, hi;
            unpack2(acc[i][j], lo, hi);
            float2 y;
            y.x = fmaxf(fmaf(a, lo, c), 0.0f);
            y.y = fmaxf(fmaf(a, hi, c), 0.0f);
            *(float2*)(xb + 2 * (pc + 32 * j)) = y;
        }
    }
}

// =====================================================================
// Kernel 2: cross-g pipelined GEMM + involution.
// it = 0..16:  GEMM(it) -> dfs[it&1]   ||   involution(it-1) <- dfs[(it-1)&1]
// involution reads fm directly from padded gmem (register row reuse).
// smem (floats): xs[64*256] @0, dfs 2x[49*256] @16384, w2 2x[49*64] @41472
// =====================================================================
#define XS_OFF   0
#define DFS_OFF  16384
#define DFS_SZ   12544
#define W2_OFF   41472
#define W2_SZ    3136
#define K2_SMEM  ((W2_OFF + 2 * W2_SZ) * 4)   // 190,976 B

__global__ void __launch_bounds__(512, 1)
k2_fused(const float* __restrict__ W2, float* __restrict__ out)
{
    extern __shared__ float sm2[];
    float* xs  = sm2 + XS_OFF;
    float* dfs = sm2 + DFS_OFF;
    float* w2s = sm2 + W2_OFF;

    const int tid  = threadIdx.x;
    const int b    = blockIdx.y;
    const int tile = blockIdx.x;
    const int ti0  = (tile / 6) * 16;
    const int tj0  = (tile % 6) * 16;

    // prefetch W2 slice g=0
    for (int i = tid; i < 784; i += 512)
        cp16(w2s + i * 4, W2 + i * 4);
    // load xs k-major via cp.async: xs[k][p] = x[b][k][pixel(p)]
    for (int i = tid; i < 4096; i += 512) {
        int k = i >> 6, p = (i & 63) * 4;
        int gi = ti0 + (p >> 4), gj = tj0 + (p & 15);
        cp16(xs + k * 256 + p, g_x + ((size_t)b * RR + k) * HWSZ + gi * WW + gj);
    }
    cp_commit();
    cp_wait<0>();
    __syncthreads();

    // GEMM mapping: 64 col-quads (4 px) x 7 row-groups (7 rows)
    const int pcq = tid & 63;
    const int rg  = tid >> 6;          // 0..7, rg==7 idle in GEMM
    // involution mapping: (row, gc, 8-px half)
    const int gc  = tid & 15;
    const int h8  = ((tid >> 4) & 1) * 8;
    const int row = tid >> 5;          // 0..15

    float* outb = out + (size_t)b * CC * HWSZ;

    for (int it = 0; it <= 16; ++it) {
        if (it < 16) {
            if (it < 15) {
                float* w2d = w2s + ((it + 1) & 1) * W2_SZ;
                const float* src = W2 + (size_t)(it + 1) * W2_SZ;
                for (int i = tid; i < 784; i += 512)
                    cp16(w2d + i * 4, src + i * 4);
                cp_commit();
            }
            // ---- GEMM(it): dfs = W2_g[49][64] @ xs[64][256] ----
            if (rg < 7) {
                const float* w2c = w2s + (it & 1) * W2_SZ + (rg * 7) * 64;
                float* dfc = dfs + (it & 1) * DFS_SZ;
                u64 acc[7][2];
#pragma unroll
                for (int i = 0; i < 7; ++i) { acc[i][0] = 0ull; acc[i][1] = 0ull; }

#pragma unroll 4
                for (int kk = 0; kk < 64; kk += 4) {
                    float4 wv[7];
#pragma unroll
                    for (int i = 0; i < 7; ++i)
                        wv[i] = *(const float4*)(w2c + i * 64 + kk);
#pragma unroll
                    for (int t = 0; t < 4; ++t) {
                        ulonglong2 xv = *(const ulonglong2*)(xs + (kk + t) * 256 + 4 * pcq);
#pragma unroll
                        for (int i = 0; i < 7; ++i) {
                            float w = (&wv[i].x)[t];
                            u64 wq = pack2(w, w);
                            fma2(acc[i][0], wq, xv.x);
                            fma2(acc[i][1], wq, xv.y);
                        }
                    }
                }
#pragma unroll
                for (int i = 0; i < 7; ++i) {
                    ulonglong2 st;
                    st.x = acc[i][0];
                    st.y = acc[i][1];
                    *(ulonglong2*)(dfc + (rg * 7 + i) * 256 + 4 * pcq) = st;
                }
            }
        }

        if (it > 0) {
            const int g = it - 1;
            const float* dfc = dfs + (g & 1) * DFS_SZ + row * 16 + h8;
            const float* fgc = g_fmp
                + ((size_t)((b * CC) + g * 16 + gc) * PH + (ti0 + row)) * PW
                + (tj0 + h8);

            u64 acc[4] = {0ull, 0ull, 0ull, 0ull};
            u64 res[4];
#pragma unroll
            for (int di = 0; di < 7; ++di) {
                const float* pr = fgc + di * PW;
                float4 v0 = *(const float4*)(pr);
                float4 v1 = *(const float4*)(pr + 4);
                float4 v2 = *(const float4*)(pr + 8);
                float4 v3 = *(const float4*)(pr + 12);
                float f[16];
                f[0]=v0.x; f[1]=v0.y; f[2]=v0.z; f[3]=v0.w;
                f[4]=v1.x; f[5]=v1.y; f[6]=v1.z; f[7]=v1.w;
                f[8]=v2.x; f[9]=v2.y; f[10]=v2.z; f[11]=v2.w;
                f[12]=v3.x; f[13]=v3.y; f[14]=v3.z; f[15]=v3.w;
#pragma unroll
                for (int dj = 0; dj < 7; ++dj) {
                    const ulonglong2* dp =
                        (const ulonglong2*)(dfc + (di * 7 + dj) * 256);
                    ulonglong2 d01 = dp[0];
                    ulonglong2 d23 = dp[1];
                    fma2(acc[0], pack2(f[0 + dj], f[1 + dj]), d01.x);
                    fma2(acc[1], pack2(f[2 + dj], f[3 + dj]), d01.y);
                    fma2(acc[2], pack2(f[4 + dj], f[5 + dj]), d23.x);
                    fma2(acc[3], pack2(f[6 + dj], f[7 + dj]), d23.y);
                }
                if (di == 3) {
#pragma unroll
                    for (int q = 0; q < 4; ++q)
                        res[q] = pack2(f[2 * q + 3], f[2 * q + 4]);
                }
            }
            float* op = outb + (size_t)(g * 16 + gc) * HWSZ
                             + (ti0 + row) * WW + tj0 + h8;
#pragma unroll
            for (int q = 0; q < 4; ++q) {
                float al, ah, rl, rh;
                unpack2(acc[q], al, ah);
                unpack2(res[q], rl, rh);
                *(float2*)(op + 2 * q) = make_float2(al + rl, ah + rh);
            }
        }

        cp_wait<0>();
        __syncthreads();
    }
}

// =====================================================================
extern "C" void kernel_launch(void* const* d_in, const int* in_sizes, int n_in,
                              void* d_out, int out_size)
{
    (void)in_sizes; (void)n_in; (void)out_size;
    const float* fm    = (const float*)d_in[0];
    const float* guide = (const float*)d_in[1];
    const float* W1    = (const float*)d_in[2];
    const float* gma   = (const float*)d_in[3];
    const float* bta   = (const float*)d_in[4];
    const float* mu    = (const float*)d_in[5];
    const float* var   = (const float*)d_in[6];
    const float* W2    = (const float*)d_in[7];
    float* out = (float*)d_out;

    cudaFuncSetAttribute(k1_gemm_bn_relu,
                         cudaFuncAttributeMaxDynamicSharedMemorySize, K1_SMEM);
    cudaFuncSetAttribute(k2_fused,
                         cudaFuncAttributeMaxDynamicSharedMemorySize, K2_SMEM);

    k0_pad<<<(PAD_TOT + 255) / 256, 256>>>(fm);
    dim3 grid(36, 8);
    k1_gemm_bn_relu<<<grid, 256, K1_SMEM>>>(guide, W1, gma, bta, mu, var);
    k2_fused<<<grid, 512, K2_SMEM>>>(W2, out);
}

// round 4
// speedup vs baseline: 1.0741x; 1.0741x over previous
#include <cuda_runtime.h>
#include <cstdint>

#define BB   8
#define CC   256
#define HH   96
#define WW   96
#define RR   64
#define HWSZ 9216
#define GG   16
#define PH   102
#define PW   104

__device__ float g_x[BB * RR * HWSZ];
__device__ float g_fmp[(size_t)BB * CC * PH * PW];

typedef unsigned long long u64;

__device__ __forceinline__ u64 pack2(float lo, float hi) {
    u64 r;
    asm("mov.b64 %0, {%1, %2};" : "=l"(r) : "f"(lo), "f"(hi));
    return r;
}
__device__ __forceinline__ void unpack2(u64 v, float& lo, float& hi) {
    asm("mov.b64 {%0, %1}, %2;" : "=f"(lo), "=f"(hi) : "l"(v));
}
__device__ __forceinline__ void fma2(u64& d, u64 a, u64 b) {
    asm("fma.rn.f32x2 %0, %1, %2, %0;" : "+l"(d) : "l"(a), "l"(b));
}

__device__ __forceinline__ unsigned s2u(const void* p) {
    return (unsigned)__cvta_generic_to_shared(p);
}
__device__ __forceinline__ void cp16(void* dst, const void* src) {
    asm volatile("cp.async.cg.shared.global [%0], [%1], 16;\n"
                 :: "r"(s2u(dst)), "l"(src));
}
__device__ __forceinline__ void cp_commit() {
    asm volatile("cp.async.commit_group;\n" ::);
}
template<int N> __device__ __forceinline__ void cp_wait() {
    asm volatile("cp.async.wait_group %0;\n" :: "n"(N));
}

// =====================================================================
// Kernel 0: zero-padded copy fm -> g_fmp[b][c][102][104]
// =====================================================================
#define PAD_TOT (BB * CC * PH * (PW / 4))

__global__ void __launch_bounds__(256)
k0_pad(const float* __restrict__ fm)
{
    int idx = blockIdx.x * 256 + threadIdx.x;
    if (idx >= PAD_TOT) return;
    int c4  = idx % (PW / 4);
    int r   = (idx / (PW / 4)) % PH;
    int ch  = idx / ((PW / 4) * PH);

    float4 v = make_float4(0.f, 0.f, 0.f, 0.f);
    int i = r - 3;
    if ((unsigned)i < 96u) {
        const float* src = fm + (size_t)ch * HWSZ + i * WW;
        int j0 = c4 * 4 - 3;
#pragma unroll
        for (int e = 0; e < 4; ++e) {
            int j = j0 + e;
            if ((unsigned)j < 96u) (&v.x)[e] = src[j];
        }
    }
    ((float4*)g_fmp)[idx] = v;
}

// =====================================================================
// Kernel 1: x = relu(bn(W1 @ guide))  (unchanged, near FMA floor)
// =====================================================================
#define K1_WS 16384
#define K1_GS 4096
#define K1_SMEM ((K1_WS + 2 * K1_GS) * 4)

__global__ void __launch_bounds__(256, 2)
k1_gemm_bn_relu(const float* __restrict__ guide, const float* __restrict__ W1,
                const float* __restrict__ gamma_, const float* __restrict__ beta_,
                const float* __restrict__ mean_, const float* __restrict__ var_)
{
    extern __shared__ float sm1[];
    float* Ws = sm1;
    float* Gs = sm1 + K1_WS;

    const int tid = threadIdx.x;
    const int b   = blockIdx.y;
    const int p0  = blockIdx.x * 256;
    const float* gb = guide + (size_t)b * CC * HWSZ + p0;

    for (int i = tid; i < 4096; i += 256)
        cp16(Ws + i * 4, W1 + i * 4);
    for (int i = tid; i < 1024; i += 256) {
        int kr = i >> 6, c4 = i & 63;
        cp16(Gs + kr * 256 + c4 * 4, gb + kr * HWSZ + c4 * 4);
    }
    cp_commit();

    u64 acc[8][4];
#pragma unroll
    for (int i = 0; i < 8; ++i)
#pragma unroll
        for (int j = 0; j < 4; ++j) acc[i][j] = 0ull;

    const int pc = tid & 31;
    const int rg = tid >> 5;

    for (int kc = 0; kc < 16; ++kc) {
        if (kc < 15) {
            float* dst = Gs + ((kc + 1) & 1) * K1_GS;
            const float* src = gb + (size_t)(kc + 1) * 16 * HWSZ;
            for (int i = tid; i < 1024; i += 256) {
                int kr = i >> 6, c4 = i & 63;
                cp16(dst + kr * 256 + c4 * 4, src + kr * HWSZ + c4 * 4);
            }
            cp_commit();
            cp_wait<1>();
        } else {
            cp_wait<0>();
        }
        __syncthreads();

        const float* G  = Gs + (kc & 1) * K1_GS;
        const float* Wr = Ws + (rg * 8) * 256 + kc * 16;
#pragma unroll
        for (int kk = 0; kk < 16; kk += 4) {
            float4 wv[8];
#pragma unroll
            for (int i = 0; i < 8; ++i)
                wv[i] = *(const float4*)(Wr + i * 256 + kk);
#pragma unroll
            for (int t = 0; t < 4; ++t) {
                u64 bv[4];
#pragma unroll
                for (int j = 0; j < 4; ++j)
                    bv[j] = *(const u64*)(G + (kk + t) * 256 + 2 * (pc + 32 * j));
#pragma unroll
                for (int i = 0; i < 8; ++i) {
                    float w = (&wv[i].x)[t];
                    u64 wq = pack2(w, w);
#pragma unroll
                    for (int j = 0; j < 4; ++j) fma2(acc[i][j], wq, bv[j]);
                }
            }
        }
        __syncthreads();
    }

#pragma unroll
    for (int i = 0; i < 8; ++i) {
        int r = rg * 8 + i;
        float a = gamma_[r] * rsqrtf(var_[r] + 1e-5f);
        float c = beta_[r] - mean_[r] * a;
        float* xb = g_x + ((size_t)b * RR + r) * HWSZ + p0;
#pragma unroll
        for (int j = 0; j < 4; ++j) {
            float lo, hi;
            unpack2(acc[i][j], lo, hi);
            float2 y;
            y.x = fmaxf(fmaf(a, lo, c), 0.0f);
            y.y = fmaxf(fmaf(a, hi, c), 0.0f);
            *(float2*)(xb + 2 * (pc + 32 * j)) = y;
        }
    }
}

// =====================================================================
// Kernel 2: cross-g pipelined.
// window it (0..16):
//   stage fm(it)->fmb[it&1], w2(it+1)->w2b[(it+1)&1] via cp.async
//   GEMM(it): dfs[it&1] = W2_it[49][64] @ x   (x via LDG.128, 2-slot lookahead)
//   inv(it-1): reads dfs[(it-1)&1], fmb[(it-1)&1]; writes out
//   cp_wait; syncthreads
// smem floats: dfs 2x12544 @0, w2 2x3136 @25088, fm 2x(16*532) @31360
// fm plane layout: [gc][22 rows][24 cols], plane stride 532 (conflict-free
// LDS.128 across gc lanes: 532*4 mod 128 = 80, gc*80 mod 128 all distinct)
// =====================================================================
#define DFS_SZ   12544
#define W2_OFF   25088
#define W2_SZ    3136
#define FM_OFF   31360
#define FM_PL    532
#define FM_SZ    (16 * FM_PL)          // 8512
#define K2_SMEM  ((FM_OFF + 2 * FM_SZ) * 4)   // 193,536 B

__global__ void __launch_bounds__(512, 1)
k2_fused(const float* __restrict__ W2, float* __restrict__ out)
{
    extern __shared__ float sm2[];
    float* dfs = sm2;
    float* w2b = sm2 + W2_OFF;
    float* fmb = sm2 + FM_OFF;

    const int tid  = threadIdx.x;
    const int b    = blockIdx.y;
    const int tile = blockIdx.x;
    const int ti0  = (tile / 6) * 16;
    const int tj0  = (tile % 6) * 16;

    // GEMM mapping
    const int pcq = tid & 63;            // 4-px quad
    const int rg  = tid >> 6;            // 0..7 (rg==7 idle in GEMM)
    const int prow = pcq >> 2, pcol = (pcq & 3) * 4;
    const float* xg = g_x + (size_t)b * RR * HWSZ
                    + (ti0 + prow) * WW + tj0 + pcol;
    // involution mapping
    const int gc  = tid & 15;
    const int h8  = ((tid >> 4) & 1) * 8;
    const int row = tid >> 5;            // 0..15

    const float* fmpb = g_fmp + (size_t)b * CC * PH * PW;
    float* outb = out + (size_t)b * CC * HWSZ;

    // preloop: stage w2(0) -> buf0
    for (int i = tid; i < 784; i += 512)
        cp16(w2b + i * 4, W2 + i * 4);
    cp_commit();
    cp_wait<0>();
    __syncthreads();

    for (int it = 0; it <= 16; ++it) {
        if (it < 16) {
            // ---- stage fm(it) -> fmb[it&1] ----
            {
                float* fmd = fmb + (it & 1) * FM_SZ;
                const float* src0 = fmpb + (size_t)(it * 16) * PH * PW;
                for (int i = tid; i < 2112; i += 512) {
                    int gcs = i / 132;
                    int rem = i - gcs * 132;
                    int ii  = rem / 6;
                    int c4  = rem - ii * 6;
                    cp16(fmd + gcs * FM_PL + ii * 24 + c4 * 4,
                         src0 + (size_t)gcs * PH * PW + (ti0 + ii) * PW + tj0 + c4 * 4);
                }
            }
            // ---- stage w2(it+1) ----
            if (it < 15) {
                float* w2d = w2b + ((it + 1) & 1) * W2_SZ;
                const float* src = W2 + (size_t)(it + 1) * W2_SZ;
                for (int i = tid; i < 784; i += 512)
                    cp16(w2d + i * 4, src + i * 4);
            }
            cp_commit();

            // ---- GEMM(it): dfs[it&1] = W2_it @ x ----
            if (rg < 7) {
                const float* w2c = w2b + (it & 1) * W2_SZ + (rg * 7) * 64;
                float* dfc = dfs + (it & 1) * DFS_SZ;
                u64 acc[7][2];
#pragma unroll
                for (int i = 0; i < 7; ++i) { acc[i][0] = 0ull; acc[i][1] = 0ull; }

                ulonglong2 xr[2][4];
#pragma unroll
                for (int t = 0; t < 4; ++t)
                    xr[0][t] = *(const ulonglong2*)(xg + (size_t)t * HWSZ);

#pragma unroll
                for (int c = 0; c < 16; ++c) {
                    const int kk = c * 4;
                    if (c < 15) {
#pragma unroll
                        for (int t = 0; t < 4; ++t)
                            xr[(c + 1) & 1][t] =
                                *(const ulonglong2*)(xg + (size_t)(kk + 4 + t) * HWSZ);
                    }
                    float4 wv[7];
#pragma unroll
                    for (int i = 0; i < 7; ++i)
                        wv[i] = *(const float4*)(w2c + i * 64 + kk);
#pragma unroll
                    for (int t = 0; t < 4; ++t) {
                        ulonglong2 xv = xr[c & 1][t];
#pragma unroll
                        for (int i = 0; i < 7; ++i) {
                            float w = (&wv[i].x)[t];
                            u64 wq = pack2(w, w);
                            fma2(acc[i][0], wq, xv.x);
                            fma2(acc[i][1], wq, xv.y);
                        }
                    }
                }
#pragma unroll
                for (int i = 0; i < 7; ++i) {
                    ulonglong2 st;
                    st.x = acc[i][0];
                    st.y = acc[i][1];
                    *(ulonglong2*)(dfc + (rg * 7 + i) * 256 + 4 * pcq) = st;
                }
            }
        }

        if (it > 0) {
            const int g = it - 1;
            const float* dfc = dfs + (g & 1) * DFS_SZ + row * 16 + h8;
            const float* fmc = fmb + (g & 1) * FM_SZ + gc * FM_PL;

            u64 acc[4] = {0ull, 0ull, 0ull, 0ull};
            u64 res[4];
#pragma unroll
            for (int di = 0; di < 7; ++di) {
                const float* pr = fmc + (row + di) * 24 + h8;
                float4 v0 = *(const float4*)(pr);
                float4 v1 = *(const float4*)(pr + 4);
                float4 v2 = *(const float4*)(pr + 8);
                float4 v3 = *(const float4*)(pr + 12);
                float f[16];
                f[0]=v0.x; f[1]=v0.y; f[2]=v0.z; f[3]=v0.w;
                f[4]=v1.x; f[5]=v1.y; f[6]=v1.z; f[7]=v1.w;
                f[8]=v2.x; f[9]=v2.y; f[10]=v2.z; f[11]=v2.w;
                f[12]=v3.x; f[13]=v3.y; f[14]=v3.z; f[15]=v3.w;
#pragma unroll
                for (int dj = 0; dj < 7; ++dj) {
                    const ulonglong2* dp =
                        (const ulonglong2*)(dfc + (di * 7 + dj) * 256);
                    ulonglong2 d01 = dp[0];
                    ulonglong2 d23 = dp[1];
                    fma2(acc[0], pack2(f[0 + dj], f[1 + dj]), d01.x);
                    fma2(acc[1], pack2(f[2 + dj], f[3 + dj]), d01.y);
                    fma2(acc[2], pack2(f[4 + dj], f[5 + dj]), d23.x);
                    fma2(acc[3], pack2(f[6 + dj], f[7 + dj]), d23.y);
                }
                if (di == 3) {
#pragma unroll
                    for (int q = 0; q < 4; ++q)
                        res[q] = pack2(f[2 * q + 3], f[2 * q + 4]);
                }
            }
            float* op = outb + (size_t)(g * 16 + gc) * HWSZ
                             + (ti0 + row) * WW + tj0 + h8;
#pragma unroll
            for (int q = 0; q < 4; ++q) {
                float al, ah, rl, rh;
                unpack2(acc[q], al, ah);
                unpack2(res[q], rl, rh);
                *(float2*)(op + 2 * q) = make_float2(al + rl, ah + rh);
            }
        }

        cp_wait<0>();
        __syncthreads();
    }
}

// =====================================================================
extern "C" void kernel_launch(void* const* d_in, const int* in_sizes, int n_in,
                              void* d_out, int out_size)
{
    (void)in_sizes; (void)n_in; (void)out_size;
    const float* fm    = (const float*)d_in[0];
    const float* guide = (const float*)d_in[1];
    const float* W1    = (const float*)d_in[2];
    const float* gma   = (const float*)d_in[3];
    const float* bta   = (const float*)d_in[4];
    const float* mu    = (const float*)d_in[5];
    const float* var   = (const float*)d_in[6];
    const float* W2    = (const float*)d_in[7];
    float* out = (float*)d_out;

    cudaFuncSetAttribute(k1_gemm_bn_relu,
                         cudaFuncAttributeMaxDynamicSharedMemorySize, K1_SMEM);
    cudaFuncSetAttribute(k2_fused,
                         cudaFuncAttributeMaxDynamicSharedMemorySize, K2_SMEM);

    k0_pad<<<(PAD_TOT + 255) / 256, 256>>>(fm);
    dim3 grid(36, 8);
    k1_gemm_bn_relu<<<grid, 256, K1_SMEM>>>(guide, W1, gma, bta, mu, var);
    k2_fused<<<grid, 512, K2_SMEM>>>(W2, out);
}

// round 5
// speedup vs baseline: 1.0906x; 1.0154x over previous
#include <cuda_runtime.h>
#include <cstdint>

#define BB   8
#define CC   256
#define HH   96
#define WW   96
#define RR   64
#define HWSZ 9216
#define GG   16
#define PH   102
#define PW   104

__device__ float g_x[BB * RR * HWSZ];
__device__ float g_fmp[(size_t)BB * CC * PH * PW];

typedef unsigned long long u64;

__device__ __forceinline__ u64 pack2(float lo, float hi) {
    u64 r;
    asm("mov.b64 %0, {%1, %2};" : "=l"(r) : "f"(lo), "f"(hi));
    return r;
}
__device__ __forceinline__ void unpack2(u64 v, float& lo, float& hi) {
    asm("mov.b64 {%0, %1}, %2;" : "=f"(lo), "=f"(hi) : "l"(v));
}
__device__ __forceinline__ void fma2(u64& d, u64 a, u64 b) {
    asm("fma.rn.f32x2 %0, %1, %2, %0;" : "+l"(d) : "l"(a), "l"(b));
}

__device__ __forceinline__ unsigned s2u(const void* p) {
    return (unsigned)__cvta_generic_to_shared(p);
}
__device__ __forceinline__ void cp16(void* dst, const void* src) {
    asm volatile("cp.async.cg.shared.global [%0], [%1], 16;\n"
                 :: "r"(s2u(dst)), "l"(src));
}
__device__ __forceinline__ void cp_commit() {
    asm volatile("cp.async.commit_group;\n" ::);
}
template<int N> __device__ __forceinline__ void cp_wait() {
    asm volatile("cp.async.wait_group %0;\n" :: "n"(N));
}

// =====================================================================
// Kernel 0: zero-padded copy fm -> g_fmp[b][c][102][104]
// =====================================================================
#define PAD_TOT (BB * CC * PH * (PW / 4))

__global__ void __launch_bounds__(256)
k0_pad(const float* __restrict__ fm)
{
    int idx = blockIdx.x * 256 + threadIdx.x;
    if (idx >= PAD_TOT) return;
    int c4  = idx % (PW / 4);
    int r   = (idx / (PW / 4)) % PH;
    int ch  = idx / ((PW / 4) * PH);

    float4 v = make_float4(0.f, 0.f, 0.f, 0.f);
    int i = r - 3;
    if ((unsigned)i < 96u) {
        const float* src = fm + (size_t)ch * HWSZ + i * WW;
        int j0 = c4 * 4 - 3;
#pragma unroll
        for (int e = 0; e < 4; ++e) {
            int j = j0 + e;
            if ((unsigned)j < 96u) (&v.x)[e] = src[j];
        }
    }
    ((float4*)g_fmp)[idx] = v;
}

// =====================================================================
// Kernel 1: x = relu(bn(W1 @ guide))  (unchanged)
// =====================================================================
#define K1_WS 16384
#define K1_GS 4096
#define K1_SMEM ((K1_WS + 2 * K1_GS) * 4)

__global__ void __launch_bounds__(256, 2)
k1_gemm_bn_relu(const float* __restrict__ guide, const float* __restrict__ W1,
                const float* __restrict__ gamma_, const float* __restrict__ beta_,
                const float* __restrict__ mean_, const float* __restrict__ var_)
{
    extern __shared__ float sm1[];
    float* Ws = sm1;
    float* Gs = sm1 + K1_WS;

    const int tid = threadIdx.x;
    const int b   = blockIdx.y;
    const int p0  = blockIdx.x * 256;
    const float* gb = guide + (size_t)b * CC * HWSZ + p0;

    for (int i = tid; i < 4096; i += 256)
        cp16(Ws + i * 4, W1 + i * 4);
    for (int i = tid; i < 1024; i += 256) {
        int kr = i >> 6, c4 = i & 63;
        cp16(Gs + kr * 256 + c4 * 4, gb + kr * HWSZ + c4 * 4);
    }
    cp_commit();

    u64 acc[8][4];
#pragma unroll
    for (int i = 0; i < 8; ++i)
#pragma unroll
        for (int j = 0; j < 4; ++j) acc[i][j] = 0ull;

    const int pc = tid & 31;
    const int rg = tid >> 5;

    for (int kc = 0; kc < 16; ++kc) {
        if (kc < 15) {
            float* dst = Gs + ((kc + 1) & 1) * K1_GS;
            const float* src = gb + (size_t)(kc + 1) * 16 * HWSZ;
            for (int i = tid; i < 1024; i += 256) {
                int kr = i >> 6, c4 = i & 63;
                cp16(dst + kr * 256 + c4 * 4, src + kr * HWSZ + c4 * 4);
            }
            cp_commit();
            cp_wait<1>();
        } else {
            cp_wait<0>();
        }
        __syncthreads();

        const float* G  = Gs + (kc & 1) * K1_GS;
        const float* Wr = Ws + (rg * 8) * 256 + kc * 16;
#pragma unroll
        for (int kk = 0; kk < 16; kk += 4) {
            float4 wv[8];
#pragma unroll
            for (int i = 0; i < 8; ++i)
                wv[i] = *(const float4*)(Wr + i * 256 + kk);
#pragma unroll
            for (int t = 0; t < 4; ++t) {
                u64 bv[4];
#pragma unroll
                for (int j = 0; j < 4; ++j)
                    bv[j] = *(const u64*)(G + (kk + t) * 256 + 2 * (pc + 32 * j));
#pragma unroll
                for (int i = 0; i < 8; ++i) {
                    float w = (&wv[i].x)[t];
                    u64 wq = pack2(w, w);
#pragma unroll
                    for (int j = 0; j < 4; ++j) fma2(acc[i][j], wq, bv[j]);
                }
            }
        }
        __syncthreads();
    }

#pragma unroll
    for (int i = 0; i < 8; ++i) {
        int r = rg * 8 + i;
        float a = gamma_[r] * rsqrtf(var_[r] + 1e-5f);
        float c = beta_[r] - mean_[r] * a;
        float* xb = g_x + ((size_t)b * RR + r) * HWSZ + p0;
#pragma unroll
        for (int j = 0; j < 4; ++j) {
            float lo, hi;
            unpack2(acc[i][j], lo, hi);
            float2 y;
            y.x = fmaxf(fmaf(a, lo, c), 0.0f);
            y.y = fmaxf(fmaf(a, hi, c), 0.0f);
            *(float2*)(xb + 2 * (pc + 32 * j)) = y;
        }
    }
}

// =====================================================================
// Kernel 2: tile = 16x8 px, cross-g pipelined, all operands in smem.
// window it (0..16):
//   stage fm(it)->fmb[it&1], w2(it+1)->w2b[(it+1)&1]   (cp.async)
//   GEMM(it): dfs[it&1][49][128] = W2_it[49][64] @ xs[64][128]
//   inv(it-1): dfs[(it-1)&1] x fmb[(it-1)&1] -> out
//   cp_wait; one __syncthreads
// smem floats: xs 8192 @0 | dfs 2x6272 @8192 | w2 2x3136 @20736 |
//              fm 2x(16 gc x 356) @27008   (plane 356: 8-lane-phase
//              conflict-free: 356*4 mod 128 = 16)
// =====================================================================
#define XS_OFF   0
#define DFS_OFF  8192
#define DFS_SZ   6272            // 49*128
#define W2_OFF   20736
#define W2_SZ    3136
#define FM_OFF   27008
#define FM_PL    356             // 22 rows * 16 cols + pad 4
#define FM_SZ    (16 * FM_PL)    // 5696
#define K2_SMEM  ((FM_OFF + 2 * FM_SZ) * 4)   // 153,600 B

__global__ void __launch_bounds__(512, 1)
k2_fused(const float* __restrict__ W2, float* __restrict__ out)
{
    extern __shared__ float sm2[];
    float* xs  = sm2 + XS_OFF;
    float* dfs = sm2 + DFS_OFF;
    float* w2b = sm2 + W2_OFF;
    float* fmb = sm2 + FM_OFF;

    const int tid  = threadIdx.x;
    const int b    = blockIdx.y;
    const int tile = blockIdx.x;          // 72 tiles: 6 (i) x 12 (j)
    const int ti0  = (tile / 12) * 16;
    const int tj0  = (tile % 12) * 8;

    // GEMM mapping: pcq = 4-px quad (0..31), rg row-group (4 rows)
    const int pcq = tid & 31;
    const int rg  = tid >> 5;             // 0..15 ; rows 4rg..4rg+3 (<49)
    // involution mapping: (row, gc, col-half)
    const int gc  = tid & 15;
    const int hf  = (tid >> 4) & 1;       // 4-px half of 8-px row
    const int row = tid >> 5;             // 0..15

    const float* fmpb = g_fmp + (size_t)b * CC * PH * PW;
    float* outb = out + (size_t)b * CC * HWSZ;

    // ---- preloop: stage w2(0) and xs ----
    for (int i = tid; i < 784; i += 512)
        cp16(w2b + i * 4, W2 + i * 4);
    {
        const float* xsrc = g_x + (size_t)b * RR * HWSZ + ti0 * WW + tj0;
        for (int i = tid; i < 2048; i += 512) {
            int k = i >> 5, q = i & 31;
            int r = q >> 1, c = (q & 1) * 4;
            cp16(xs + k * 128 + q * 4, xsrc + (size_t)k * HWSZ + r * WW + c);
        }
    }
    cp_commit();
    cp_wait<0>();
    __syncthreads();

    for (int it = 0; it <= 16; ++it) {
        if (it < 16) {
            // ---- stage fm(it): 16 gc x 22 rows x 16 cols ----
            {
                float* fmd = fmb + (it & 1) * FM_SZ;
                const float* src0 = fmpb + (size_t)(it * 16) * PH * PW
                                  + ti0 * PW + tj0;
                for (int i = tid; i < 1408; i += 512) {
                    int gcs = i / 88;
                    int rem = i - gcs * 88;
                    int ii  = rem >> 2;
                    int c   = (rem & 3) * 4;
                    cp16(fmd + gcs * FM_PL + ii * 16 + c,
                         src0 + (size_t)gcs * PH * PW + ii * PW + c);
                }
            }
            // ---- stage w2(it+1) ----
            if (it < 15) {
                float* w2d = w2b + ((it + 1) & 1) * W2_SZ;
                const float* src = W2 + (size_t)(it + 1) * W2_SZ;
                for (int i = tid; i < 784; i += 512)
                    cp16(w2d + i * 4, src + i * 4);
            }
            cp_commit();

            // ---- GEMM(it): dfs[it&1] = W2_it[49][64] @ xs[64][128] ----
            const int r0 = rg * 4;
            if (r0 < 49) {
                const float* w2c = w2b + (it & 1) * W2_SZ;
                float* dfc = dfs + (it & 1) * DFS_SZ;
                u64 acc[4][2];
#pragma unroll
                for (int i = 0; i < 4; ++i) { acc[i][0] = 0ull; acc[i][1] = 0ull; }

#pragma unroll 4
                for (int kk = 0; kk < 64; kk += 4) {
                    float4 wv[4];
#pragma unroll
                    for (int i = 0; i < 4; ++i) {
                        int rr = r0 + i; rr = rr < 49 ? rr : 48;
                        wv[i] = *(const float4*)(w2c + rr * 64 + kk);
                    }
#pragma unroll
                    for (int t = 0; t < 4; ++t) {
                        ulonglong2 xv = *(const ulonglong2*)(xs + (kk + t) * 128 + 4 * pcq);
#pragma unroll
                        for (int i = 0; i < 4; ++i) {
                            float w = (&wv[i].x)[t];
                            u64 wq = pack2(w, w);
                            fma2(acc[i][0], wq, xv.x);
                            fma2(acc[i][1], wq, xv.y);
                        }
                    }
                }
#pragma unroll
                for (int i = 0; i < 4; ++i) {
                    if (r0 + i < 49) {
                        ulonglong2 st;
                        st.x = acc[i][0];
                        st.y = acc[i][1];
                        *(ulonglong2*)(dfc + (r0 + i) * 128 + 4 * pcq) = st;
                    }
                }
            }
        }

        if (it > 0) {
            const int g = it - 1;
            const float* dfc = dfs + (g & 1) * DFS_SZ + row * 8 + 4 * hf;
            const float* fmc = fmb + (g & 1) * FM_SZ + gc * FM_PL + 4 * hf;

            u64 acc[2] = {0ull, 0ull};
            u64 res[2];
#pragma unroll
            for (int di = 0; di < 7; ++di) {
                const float* pr = fmc + (row + di) * 16;
                float4 v0 = *(const float4*)(pr);
                float4 v1 = *(const float4*)(pr + 4);
                float4 v2 = *(const float4*)(pr + 8);
                float f[12];
                f[0]=v0.x; f[1]=v0.y; f[2]=v0.z; f[3]=v0.w;
                f[4]=v1.x; f[5]=v1.y; f[6]=v1.z; f[7]=v1.w;
                f[8]=v2.x; f[9]=v2.y; f[10]=v2.z; f[11]=v2.w;
#pragma unroll
                for (int dj = 0; dj < 7; ++dj) {
                    ulonglong2 d = *(const ulonglong2*)(dfc + (di * 7 + dj) * 128);
                    fma2(acc[0], pack2(f[0 + dj], f[1 + dj]), d.x);
                    fma2(acc[1], pack2(f[2 + dj], f[3 + dj]), d.y);
                }
                if (di == 3) {
                    res[0] = pack2(f[3], f[4]);
                    res[1] = pack2(f[5], f[6]);
                }
            }
            float* op = outb + (size_t)(g * 16 + gc) * HWSZ
                             + (ti0 + row) * WW + tj0 + 4 * hf;
#pragma unroll
            for (int q = 0; q < 2; ++q) {
                float al, ah, rl, rh;
                unpack2(acc[q], al, ah);
                unpack2(res[q], rl, rh);
                *(float2*)(op + 2 * q) = make_float2(al + rl, ah + rh);
            }
        }

        cp_wait<0>();
        __syncthreads();
    }
}

// =====================================================================
extern "C" void kernel_launch(void* const* d_in, const int* in_sizes, int n_in,
                              void* d_out, int out_size)
{
    (void)in_sizes; (void)n_in; (void)out_size;
    const float* fm    = (const float*)d_in[0];
    const float* guide = (const float*)d_in[1];
    const float* W1    = (const float*)d_in[2];
    const float* gma   = (const float*)d_in[3];
    const float* bta   = (const float*)d_in[4];
    const float* mu    = (const float*)d_in[5];
    const float* var   = (const float*)d_in[6];
    const float* W2    = (const float*)d_in[7];
    float* out = (float*)d_out;

    cudaFuncSetAttribute(k1_gemm_bn_relu,
                         cudaFuncAttributeMaxDynamicSharedMemorySize, K1_SMEM);
    cudaFuncSetAttribute(k2_fused,
                         cudaFuncAttributeMaxDynamicSharedMemorySize, K2_SMEM);

    k0_pad<<<(PAD_TOT + 255) / 256, 256>>>(fm);
    dim3 grid1(36, 8);
    k1_gemm_bn_relu<<<grid1, 256, K1_SMEM>>>(guide, W1, gma, bta, mu, var);
    dim3 grid2(72, 8);
    k2_fused<<<grid2, 512, K2_SMEM>>>(W2, out);
}